// round 7
// baseline (speedup 1.0000x reference)
#include <cuda_runtime.h>
#include <math.h>

// ISTFT: BC=64; F=513; T=1024; n_fft=1024; hop=256.
// One warp = one frame: irfft(1024) via half-size 512-pt complex inverse FFT,
// 512 = 2*16*16. Exchanges: one shfl_xor(16) pass + one padded-smem pass.
// All twiddles/window from smem tables (no serial rotation chains).

#define FPC 8                 // frames per CTA (one per warp, 256 threads)
#define BUFS 550              // per-frame staging stride (f2): pack conflict-free, holds 545
#define ACC_F2 1408           // 128*7 + 512
#define ACC_FLOATS 2816
#define INT_LO_F 768          // exclusively-owned interior of acc (floats)
#define INT_HI_F 2048
#define OUT_PER_BC 262400

// dynamic smem layout (float2 units)
#define OFF_BUF  0
#define OFF_ACC  (FPC * BUFS)                  // 4400
#define OFF_TW   (OFF_ACC + ACC_F2)            // 5808
#define OFF_HANN (OFF_TW + 1024)               // 6832
#define SMEM_F2  (OFF_HANN + 512)              // 7344 f2 = 58752 B

__device__ __forceinline__ float2 cmul(float2 a, float2 b) {
    return make_float2(a.x * b.x - a.y * b.y, a.x * b.y + a.y * b.x);
}
__device__ __forceinline__ float2 cadd(float2 a, float2 b) { return make_float2(a.x + b.x, a.y + b.y); }
__device__ __forceinline__ float2 csub(float2 a, float2 b) { return make_float2(a.x - b.x, a.y - b.y); }
__device__ __forceinline__ float2 cmuli(float2 a) { return make_float2(-a.y, a.x); }  // * i

// inverse radix-4: y[u] = sum_t x[t] * i^{ut}
__device__ __forceinline__ void r4i(float2 a, float2 b, float2 c, float2 d, float2 y[4]) {
    float2 t0 = cadd(a, c), t1 = csub(a, c);
    float2 t2 = cadd(b, d), t3 = cmuli(csub(b, d));
    y[0] = cadd(t0, t2); y[1] = cadd(t1, t3); y[2] = csub(t0, t2); y[3] = csub(t1, t3);
}

// inverse radix-16 in registers: y[u] = sum_t x[t] e^{+2 pi i u t/16}
__device__ __forceinline__ void bfly16(const float2 x[16], float2 y[16]) {
    const float c1 = 0.92387953251128675f, s1 = 0.38268343236508977f, r2 = 0.70710678118654752f;
    const float2 W1 = make_float2(c1, s1), W2 = make_float2(r2, r2), W3 = make_float2(s1, c1);
    const float2 W6 = make_float2(-r2, r2), W9 = make_float2(-c1, -s1);
    float2 A0[4], A1[4], A2[4], A3[4], t[4];
    r4i(x[0], x[4], x[8],  x[12], A0);
    r4i(x[1], x[5], x[9],  x[13], A1);
    r4i(x[2], x[6], x[10], x[14], A2);
    r4i(x[3], x[7], x[11], x[15], A3);
    A1[1] = cmul(A1[1], W1); A1[2] = cmul(A1[2], W2); A1[3] = cmul(A1[3], W3);
    A2[1] = cmul(A2[1], W2); A2[2] = cmuli(A2[2]);    A2[3] = cmul(A2[3], W6);
    A3[1] = cmul(A3[1], W3); A3[2] = cmul(A3[2], W6); A3[3] = cmul(A3[3], W9);
    r4i(A0[0], A1[0], A2[0], A3[0], t); y[0] = t[0]; y[4] = t[1]; y[8]  = t[2]; y[12] = t[3];
    r4i(A0[1], A1[1], A2[1], A3[1], t); y[1] = t[0]; y[5] = t[1]; y[9]  = t[2]; y[13] = t[3];
    r4i(A0[2], A1[2], A2[2], A3[2], t); y[2] = t[0]; y[6] = t[1]; y[10] = t[2]; y[14] = t[3];
    r4i(A0[3], A1[3], A2[3], A3[3], t); y[3] = t[0]; y[7] = t[1]; y[11] = t[2]; y[15] = t[3];
}

__global__ void __launch_bounds__(256, 2) istft_kernel(const float2* __restrict__ in,
                                                       float* __restrict__ out) {
    extern __shared__ float2 sm[];
    float2* buf   = sm + OFF_BUF;    // pack staging + B->C exchange (per-frame stride BUFS)
    float2* acc2  = sm + OFF_ACC;    // overlap-add accumulator
    float2* tw    = sm + OFF_TW;     // e^{+2 pi i k/1024}, k=0..1023
    float2* hannp = sm + OFF_HANN;   // (hann(2m), hann(2m+1)), m=0..511

    const int tid = threadIdx.x;
    const int l = tid & 31;              // lane
    const int jf = tid >> 5;             // frame (warp) index, 0..7
    const int bc = blockIdx.y;
    const int tbase = blockIdx.x * FPC;

    // ---- tables + zero edge chunks of acc ----
    for (int i = tid; i < 1024; i += 256) {
        float s, c;
        __sincosf(6.283185307179586f * (float)i / 1024.0f, &s, &c);
        tw[i] = make_float2(c, s);
    }
    for (int i = tid; i < 512; i += 256) {
        float c0 = __cosf(6.283185307179586f * (float)(2 * i) / 1024.0f);
        float c1 = __cosf(6.283185307179586f * (float)(2 * i + 1) / 1024.0f);
        hannp[i] = make_float2(0.5f - 0.5f * c0, 0.5f - 0.5f * c1);
    }
    for (int i = tid; i < 384; i += 256) {
        acc2[i] = make_float2(0.f, 0.f);
        acc2[1024 + i] = make_float2(0.f, 0.f);
    }
    __syncthreads();

    // ---- pack: C2R -> half-size C2C, coalesced gmem reads, each bin once ----
    {
        const float SC = 0.015625f;   // 1/2 pack * 1/512 ifft * sqrt(1024) * 1/2 coeff
        const float2* base = in + (size_t)bc * 513 * 1024 + tbase;
        for (int idx = tid; idx < 257 * 8; idx += 256) {
            int f = idx >> 3, j = idx & 7;
            float2 X = base[(size_t)f * 1024 + j];
            float2 Y = base[(size_t)(512 - f) * 1024 + j];
            if (f == 0) { X.y = 0.f; Y.y = 0.f; }    // c2r: Im(X[0]), Im(X[512]) ignored
            float2 w = tw[f];
            float2 A = make_float2(X.x + Y.x, X.y - Y.y);   // X[f] + conj(X[512-f])
            float2 D = make_float2(X.x - Y.x, X.y + Y.y);   // X[f] - conj(X[512-f])
            float2 wD = cmul(w, D);
            buf[j * BUFS + f] = make_float2((A.x - wD.y) * SC, (A.y + wD.x) * SC);
            if (f > 0 && f < 256)
                buf[j * BUFS + (512 - f)] = make_float2((A.x + wD.y) * SC, (-A.y + wD.x) * SC);
        }
    }
    __syncthreads();

    // ============ warp-local 512-pt inverse FFT (f = f0 + 16 f1 + 256 f2) ============
    const int h = l >> 4;        // m2 after phase A
    const int f0 = l & 15;

    // Phase A: radix-2 over f2, twiddle e^{2 pi i m2 * 16 f1 / 512}, f1 = h + 2v
    //   index = (32h + 64v) in the /1024 table  [FIX: was h*(32+64v), wrong for h=0]
    float2 U0[8], U1[8];
    #pragma unroll
    for (int v = 0; v < 8; v++) {
        float2 x = buf[jf * BUFS + l + 32 * v];
        float2 y = buf[jf * BUFS + l + 32 * v + 256];
        U0[v] = cadd(x, y);
        U1[v] = cmul(csub(x, y), tw[32 * h + 64 * v]);
    }

    // A->B exchange (pairs l <-> l^16): lane (m2, f0) gathers all 16 f1
    float2 W[16];
    #pragma unroll
    for (int v = 0; v < 8; v++) {
        float2 send = h ? U0[v] : U1[v];
        float2 got;
        got.x = __shfl_xor_sync(0xffffffffu, send.x, 16);
        got.y = __shfl_xor_sync(0xffffffffu, send.y, 16);
        W[2 * v]     = h ? got   : U0[v];
        W[2 * v + 1] = h ? U1[v] : got;
    }

    // Phase B: radix-16 over f1, twiddle e^{2 pi i (m2 + 2 m1) f0/512} (table, independent LDS)
    float2 V[16];
    bfly16(W, V);
    #pragma unroll
    for (int m1 = 0; m1 < 16; m1++)
        V[m1] = cmul(V[m1], tw[2 * (h + 2 * m1) * f0]);

    // B->C exchange through padded smem: write (f0, m1, m2), read fixed (m1, m2) over f0
    __syncthreads();   // buf reuse: all pack-phase reads (phase A) are complete in all warps
    {
        float2* fb = buf + jf * BUFS;
        #pragma unroll
        for (int m1 = 0; m1 < 16; m1++)
            fb[f0 + 17 * m1 + 274 * h] = V[m1];
        __syncwarp();
        const int m1n = l & 15, m2n = l >> 4;
        #pragma unroll
        for (int t = 0; t < 16; t++)
            W[t] = fb[t + 17 * m1n + 274 * m2n];
    }

    // Phase C: radix-16 over f0 -> Z[m0] = z[q + 32 m0], q = m2 + 2 m1
    float2 Z[16];
    bfly16(W, Z);
    const int q = (l >> 4) + 2 * (l & 15);    // bijection over lanes

    // ---- Hann window from pair table: x[2m] = Re z * h(2m), x[2m+1] = Im z * h(2m+1) ----
    #pragma unroll
    for (int m0 = 0; m0 < 16; m0++) {
        float2 hh = hannp[q + 32 * m0];
        Z[m0].x *= hh.x;
        Z[m0].y *= hh.y;
    }

    // ---- OLA: 4 rounds, chunk c=(r+2jf)&3 (Latin: regions jf+c distinct per round).
    //      Round 0 touch is every region's first -> plain store for interior regions. ----
    const int accbase = 128 * jf + q;
#define OLA4(C)                                                                      \
    {                                                                                \
        float2* p = &acc2[accbase + ((C) << 7)];                                     \
        if (store) { p[0] = Z[4*(C)]; p[32] = Z[4*(C)+1]; p[64] = Z[4*(C)+2]; p[96] = Z[4*(C)+3]; } \
        else { p[0] = cadd(p[0], Z[4*(C)]); p[32] = cadd(p[32], Z[4*(C)+1]);          \
               p[64] = cadd(p[64], Z[4*(C)+2]); p[96] = cadd(p[96], Z[4*(C)+3]); }    \
    }
    #pragma unroll
    for (int r = 0; r < 4; r++) {
        int c = (r + 2 * jf) & 3;
        int region = jf + c;
        bool store = (r == 0) && (region >= 3) && (region < 8);
        if (c == 0) OLA4(0)
        else if (c == 1) OLA4(1)
        else if (c == 2) OLA4(2)
        else OLA4(3)
        __syncthreads();
    }
#undef OLA4

    // ---- writeout: interior exclusively owned -> store; edges -> atomicAdd ----
    const float* accf = (const float*)acc2;
    float* obase = out + (size_t)bc * OUT_PER_BC;
    const int q0 = tbase << 8;   // 256 * tbase
    for (int idx = tid; idx < ACC_FLOATS; idx += 256) {
        int qq = q0 + idx;
        if (qq < 512) continue;              // crop y[:, :512]
        float v = accf[idx];
        int p = qq - 512;
        if (idx >= INT_LO_F && idx < INT_HI_F) obase[p] = v;
        else atomicAdd(&obase[p], v);
    }
}

extern "C" void kernel_launch(void* const* d_in, const int* in_sizes, int n_in,
                              void* d_out, int out_size) {
    const float2* in = (const float2*)d_in[0];
    float* out = (float*)d_out;
    const int smem_bytes = SMEM_F2 * sizeof(float2);   // 58752
    cudaFuncSetAttribute(istft_kernel, cudaFuncAttributeMaxDynamicSharedMemorySize, smem_bytes);
    // zero output (edge atomics require it; interior is overwritten by plain stores)
    cudaMemsetAsync(d_out, 0, (size_t)out_size * sizeof(float), 0);
    dim3 grid(1024 / FPC, 64);   // (t-groups, bc)
    istft_kernel<<<grid, 256, smem_bytes>>>(in, out);
}

// round 8
// speedup vs baseline: 1.0438x; 1.0438x over previous
#include <cuda_runtime.h>
#include <math.h>

// ISTFT: BC=64; F=513; T=1024; n_fft=1024; hop=256.
// R4 structure (4 frames in flight, 64-thread team per frame, radix-8 Stockham
// x3 in smem) + team-scoped named barriers, table twiddles/window, f2 writeout.

#define FRAMES_PER_CTA 16
#define GROUPS 4
#define ACC_F2  2432          // 4864 floats
#define INT_LO2 384           // exclusively-owned interior of acc (f2 units)
#define INT_HI2 2048
#define OUT_PER_BC 262400

// dynamic smem layout (float2 units)
#define N_BUF   (4 * 577)                     // 2308
#define OFF_ACC N_BUF                         // 2308
#define OFF_TW  (OFF_ACC + ACC_F2)            // 4740
#define OFF_HN  (OFF_TW + 1024)               // 5764
#define SMEM_F2 (OFF_HN + 512)                // 6276 f2 = 50208 B

__device__ __forceinline__ float2 cmul(float2 a, float2 b) {
    return make_float2(a.x * b.x - a.y * b.y, a.x * b.y + a.y * b.x);
}
__device__ __forceinline__ float2 cadd(float2 a, float2 b) { return make_float2(a.x + b.x, a.y + b.y); }
__device__ __forceinline__ float2 csub(float2 a, float2 b) { return make_float2(a.x - b.x, a.y - b.y); }
__device__ __forceinline__ float2 cmuli(float2 a) { return make_float2(-a.y, a.x); }  // * i

__device__ __forceinline__ int P(int i) { return i + (i >> 3); }  // smem pad swizzle

__device__ __forceinline__ void teambar(int id) {      // 64-thread (2-warp) barrier
    asm volatile("bar.sync %0, %1;" :: "r"(id), "r"(64) : "memory");
}

// radix-8 inverse butterfly: b[u] = sum_t a[t] * e^{+2*pi*i*t*u/8}
__device__ __forceinline__ void bfly8(const float2* a, float2* b) {
    const float r = 0.70710678118654752f;
    float2 p0 = cadd(a[0], a[4]), p1 = csub(a[0], a[4]);
    float2 p2 = cadd(a[2], a[6]), p3 = cmuli(csub(a[2], a[6]));
    float2 e0 = cadd(p0, p2), e2 = csub(p0, p2), e1 = cadd(p1, p3), e3 = csub(p1, p3);
    float2 q0 = cadd(a[1], a[5]), q1 = csub(a[1], a[5]);
    float2 q2 = cadd(a[3], a[7]), q3 = cmuli(csub(a[3], a[7]));
    float2 o0 = cadd(q0, q2), o2 = csub(q0, q2), o1 = cadd(q1, q3), o3 = csub(q1, q3);
    b[0] = cadd(e0, o0); b[4] = csub(e0, o0);
    float2 w1 = make_float2(r, r), w3 = make_float2(-r, r);
    float2 t1 = cmul(o1, w1); b[1] = cadd(e1, t1); b[5] = csub(e1, t1);
    float2 t2 = cmuli(o2);    b[2] = cadd(e2, t2); b[6] = csub(e2, t2);
    float2 t3 = cmul(o3, w3); b[3] = cadd(e3, t3); b[7] = csub(e3, t3);
}

__global__ void __launch_bounds__(256, 4) istft_kernel(const float2* __restrict__ in,
                                                       float* __restrict__ out) {
    extern __shared__ float2 sm[];
    float2 (*buf)[577] = (float2(*)[577])sm;   // per-frame FFT workspace
    float2* acc2  = sm + OFF_ACC;              // overlap-add accumulator
    float2* tw    = sm + OFF_TW;               // e^{+2 pi i k/1024}, k=0..1023
    float2* hannp = sm + OFF_HN;               // (hann(2m), hann(2m+1)), m=0..511

    const int tid = threadIdx.x;
    const int bc = blockIdx.y;
    const int tbase = blockIdx.x * FRAMES_PER_CTA;

    // ---- tables; zero only the add-only front edge of acc (f2 [0,384)) ----
    for (int i = tid; i < 1024; i += 256) {
        float s, c;
        __sincosf(6.283185307179586f * (float)i / 1024.0f, &s, &c);
        tw[i] = make_float2(c, s);
    }
    for (int i = tid; i < 512; i += 256) {
        float c0 = __cosf(6.283185307179586f * (float)(2 * i) / 1024.0f);
        float c1 = __cosf(6.283185307179586f * (float)(2 * i + 1) / 1024.0f);
        hannp[i] = make_float2(0.5f - 0.5f * c0, 0.5f - 0.5f * c1);
    }
    for (int i = tid; i < 384; i += 256) acc2[i] = make_float2(0.f, 0.f);
    __syncthreads();

    const int jf = tid >> 6;   // frame within group of 4 (team id)
    const int lt = tid & 63;   // lane within 64-thread FFT team
    const int jj = lt >> 3, kk = lt & 7;
    const float SC = 0.015625f;   // 1/2 pack * 1/512 ifft * sqrt(1024) * 1/2 coeff

    for (int g = 0; g < GROUPS; g++) {
        // ---- load spectra + C2R pack fused (each bin read once, coalesced) ----
        {
            const int t0 = tbase + 4 * g;
            const float2* base = in + (size_t)bc * 513 * 1024 + t0;
            for (int idx = tid; idx < 257 * 4; idx += 256) {
                int f = idx >> 2, j = idx & 3;
                float2 X = base[(size_t)f * 1024 + j];
                float2 Y = base[(size_t)(512 - f) * 1024 + j];
                if (f == 0) { X.y = 0.f; Y.y = 0.f; }   // c2r: Im(X[0]), Im(X[512]) ignored
                float2 w = tw[f];
                float2 A = make_float2(X.x + Y.x, X.y - Y.y);   // X[f] + conj(X[512-f])
                float2 D = make_float2(X.x - Y.x, X.y + Y.y);   // X[f] - conj(X[512-f])
                float2 wD = cmul(w, D);
                buf[j][P(f)] = make_float2((A.x - wD.y) * SC, (A.y + wD.x) * SC);
                if (f > 0 && f < 256)   // partner C[512-f] from same registers (w' = -conj w)
                    buf[j][P(512 - f)] = make_float2((A.x + wD.y) * SC, (-A.y + wD.x) * SC);
            }
        }
        __syncthreads();

        float2 a[8], b[8];

        // ---- stage 0: l=1, no twiddles. Each thread writes exactly the slots
        //      it read -> no barrier between read and write. ----
        #pragma unroll
        for (int r_ = 0; r_ < 8; r_++) a[r_] = buf[jf][P(lt + (r_ << 6))];
        bfly8(a, b);
        #pragma unroll
        for (int u = 0; u < 8; u++) buf[jf][P(lt + (u << 6))] = b[u];
        teambar(jf + 1);

        // ---- stage 1: l=8, twiddles e^{2 pi i * 8 jj t / 512} from table ----
        #pragma unroll
        for (int t = 0; t < 8; t++) a[t] = buf[jf][P(kk + 64 * jj + 8 * t)];
        teambar(jf + 1);
        #pragma unroll
        for (int t = 1; t < 8; t++) a[t] = cmul(a[t], tw[(16 * jj * t) & 1023]);
        bfly8(a, b);
        #pragma unroll
        for (int u = 0; u < 8; u++) buf[jf][P(kk + 8 * jj + 64 * u)] = b[u];
        teambar(jf + 1);

        // ---- stage 2: l=64, twiddles e^{2 pi i * lt t / 512} from table ----
        #pragma unroll
        for (int t = 0; t < 8; t++) a[t] = buf[jf][P(8 * lt + t)];
        #pragma unroll
        for (int t = 1; t < 8; t++) a[t] = cmul(a[t], tw[(2 * lt * t) & 1023]);
        bfly8(a, b);   // b[u] = z[lt + 64u]; even sample in .x, odd in .y

        // ---- Hann window from pair table ----
        #pragma unroll
        for (int u = 0; u < 8; u++) {
            float2 hh = hannp[lt + (u << 6)];
            b[u].x *= hh.x;
            b[u].y *= hh.y;
        }

        // ---- OLA (R4-proven): store top chunks 6,7 (region first-touch), then
        //      3 Latin-square add rounds; regions jf+c distinct per round. ----
        const int offh = ((g << 2) + jf) << 7;   // 128*(4g+jf) in f2 units
        {
            acc2[offh + lt + (6 << 6)] = b[6];
            acc2[offh + lt + (7 << 6)] = b[7];
        }
        __syncthreads();
        #pragma unroll
        for (int rr = 0; rr < 3; rr++) {
            int c = (rr + 2 * jf) & 3;
            if (c == 3) c = 3;   // c in 0..3; chunk pairs below
            #pragma unroll
            for (int h = 0; h < 2; h++) {
                int u = 2 * c + h;
                if (u < 6) {     // chunks 6,7 already stored
                    int m = lt + (u << 6);
                    float2 v = acc2[offh + m];
                    v.x += b[u].x; v.y += b[u].y;
                    acc2[offh + m] = v;
                }
            }
            __syncthreads();
        }
        // final round for the c value not yet done (each frame does c=0..3 over 4 rounds)
        {
            int c = (3 + 2 * jf) & 3;
            #pragma unroll
            for (int h = 0; h < 2; h++) {
                int u = 2 * c + h;
                if (u < 6) {
                    int m = lt + (u << 6);
                    float2 v = acc2[offh + m];
                    v.x += b[u].x; v.y += b[u].y;
                    acc2[offh + m] = v;
                }
            }
            __syncthreads();
        }
    }

    // ---- writeout (f2): interior exclusively owned -> store; edges -> atomicAdd ----
    float* obase = out + (size_t)bc * OUT_PER_BC;
    const int q0 = tbase << 8;   // 256 * tbase (floats)
    for (int idx2 = tid; idx2 < ACC_F2; idx2 += 256) {
        int qf = q0 + 2 * idx2;
        if (qf < 512) continue;              // crop y[:, :512]
        float2 v = acc2[idx2];
        int p = qf - 512;
        if (idx2 >= INT_LO2 && idx2 < INT_HI2) {
            *(float2*)(obase + p) = v;
        } else {
            atomicAdd(&obase[p], v.x);
            atomicAdd(&obase[p + 1], v.y);
        }
    }
}

extern "C" void kernel_launch(void* const* d_in, const int* in_sizes, int n_in,
                              void* d_out, int out_size) {
    const float2* in = (const float2*)d_in[0];
    float* out = (float*)d_out;
    const int smem_bytes = SMEM_F2 * sizeof(float2);   // 50208
    cudaFuncSetAttribute(istft_kernel, cudaFuncAttributeMaxDynamicSharedMemorySize, smem_bytes);
    // zero output (edge atomics require it; interior is overwritten by plain stores)
    cudaMemsetAsync(d_out, 0, (size_t)out_size * sizeof(float), 0);
    dim3 grid(1024 / FRAMES_PER_CTA, 64);   // (t-groups, bc)
    istft_kernel<<<grid, 256, smem_bytes>>>(in, out);
}

// round 9
// speedup vs baseline: 1.3162x; 1.2610x over previous
#include <cuda_runtime.h>
#include <math.h>

// ISTFT: BC=64; F=513; T=1024; n_fft=1024; hop=256.
// R4-proven core: 4 frames in flight, 64-thread team per frame, radix-8
// Stockham x3 in smem, rotation-chain twiddles, smem OLA.
// New: deterministic edge strips via __device__ scratch + tiny add kernel
// (removes output memset and all global atomics).

#define FRAMES_PER_CTA 16
#define GROUPS 4
#define ACC_LEN 4864      // 256*15 + 1024 floats
#define ACC_F2  2432
#define OUT_PER_BC 262400
#define EDGE_LEN 768      // inter-CTA overlap (floats)
#define NBLK 64           // t-group blocks per bc

__device__ float edge_buf[64 * (NBLK - 1) * EDGE_LEN];   // 12.4 MB scratch

__device__ __forceinline__ float2 cmul(float2 a, float2 b) {
    return make_float2(a.x * b.x - a.y * b.y, a.x * b.y + a.y * b.x);
}
__device__ __forceinline__ float2 cadd(float2 a, float2 b) { return make_float2(a.x + b.x, a.y + b.y); }
__device__ __forceinline__ float2 csub(float2 a, float2 b) { return make_float2(a.x - b.x, a.y - b.y); }
__device__ __forceinline__ float2 cmuli(float2 a) { return make_float2(-a.y, a.x); }  // * i

__device__ __forceinline__ int P(int i) { return i + (i >> 3); }  // smem pad swizzle

// radix-8 inverse butterfly: b[u] = sum_t a[t] * e^{+2*pi*i*t*u/8}
__device__ __forceinline__ void bfly8(const float2* a, float2* b) {
    const float r = 0.70710678118654752f;
    float2 p0 = cadd(a[0], a[4]), p1 = csub(a[0], a[4]);
    float2 p2 = cadd(a[2], a[6]), p3 = cmuli(csub(a[2], a[6]));
    float2 e0 = cadd(p0, p2), e2 = csub(p0, p2), e1 = cadd(p1, p3), e3 = csub(p1, p3);
    float2 q0 = cadd(a[1], a[5]), q1 = csub(a[1], a[5]);
    float2 q2 = cadd(a[3], a[7]), q3 = cmuli(csub(a[3], a[7]));
    float2 o0 = cadd(q0, q2), o2 = csub(q0, q2), o1 = cadd(q1, q3), o3 = csub(q1, q3);
    b[0] = cadd(e0, o0); b[4] = csub(e0, o0);
    float2 w1 = make_float2(r, r), w3 = make_float2(-r, r);
    float2 t1 = cmul(o1, w1); b[1] = cadd(e1, t1); b[5] = csub(e1, t1);
    float2 t2 = cmuli(o2);    b[2] = cadd(e2, t2); b[6] = csub(e2, t2);
    float2 t3 = cmul(o3, w3); b[3] = cadd(e3, t3); b[7] = csub(e3, t3);
}

__global__ void __launch_bounds__(256) istft_kernel(const float2* __restrict__ in,
                                                    float* __restrict__ out) {
    __shared__ float2 buf[4][577];     // per-frame FFT workspace
    __shared__ float2 acc2[ACC_F2];    // overlap-add accumulator
    __shared__ float2 tw512[512];      // e^{+2pi i k/512}
    __shared__ float2 tw1024[513];     // e^{+2pi i k/1024}

    const int tid = threadIdx.x;
    const int bc = blockIdx.y;
    const int xb = blockIdx.x;
    const int tbase = xb * FRAMES_PER_CTA;

    // ---- init tables; zero only the add-only head (f2 [0,384)) ----
    for (int i = tid; i < 512; i += 256) {
        float s, c;
        sincosf((float)(6.283185307179586 * i / 512.0), &s, &c);
        tw512[i] = make_float2(c, s);
    }
    for (int i = tid; i < 513; i += 256) {
        float s, c;
        sincosf((float)(6.283185307179586 * i / 1024.0), &s, &c);
        tw1024[i] = make_float2(c, s);
    }
    for (int i = tid; i < 384; i += 256) acc2[i] = make_float2(0.f, 0.f);
    __syncthreads();

    const int jf = tid >> 6;   // frame within group of 4
    const int lt = tid & 63;   // lane within frame's 64-thread FFT team
    const int jj = lt >> 3, kk = lt & 7;
    const float SC = 0.015625f;   // 1/2 pack * 1/512 ifft * sqrt(1024) * 1/2 coeff

    for (int g = 0; g < GROUPS; g++) {
        // ---- load spectra + C2R pack fused (each bin read once, coalesced) ----
        {
            const int t0 = tbase + 4 * g;
            const float2* base = in + (size_t)bc * 513 * 1024 + t0;
            for (int idx = tid; idx < 257 * 4; idx += 256) {
                int f = idx >> 2, j = idx & 3;
                float2 X = base[(size_t)f * 1024 + j];
                float2 Y = base[(size_t)(512 - f) * 1024 + j];
                if (f == 0) { X.y = 0.f; Y.y = 0.f; }   // c2r: Im(X[0]), Im(X[512]) ignored
                float2 w = tw1024[f];
                float2 A = make_float2(X.x + Y.x, X.y - Y.y);   // X[f] + conj(X[512-f])
                float2 D = make_float2(X.x - Y.x, X.y + Y.y);   // X[f] - conj(X[512-f])
                float2 wD = cmul(w, D);
                buf[j][P(f)] = make_float2((A.x - wD.y) * SC, (A.y + wD.x) * SC);
                if (f > 0 && f < 256)   // partner C[512-f] from same registers (w' = -conj w)
                    buf[j][P(512 - f)] = make_float2((A.x + wD.y) * SC, (-A.y + wD.x) * SC);
            }
        }
        __syncthreads();

        float2 a[8], b[8];

        // ---- stage 0: l=1, no twiddles ----
        #pragma unroll
        for (int r_ = 0; r_ < 8; r_++) a[r_] = buf[jf][P(lt + (r_ << 6))];
        __syncthreads();
        bfly8(a, b);
        #pragma unroll
        for (int u = 0; u < 8; u++) buf[jf][P(lt + (u << 6))] = b[u];
        __syncthreads();

        // ---- stage 1: l=8, twiddles by register rotation from tw512[8*jj] ----
        #pragma unroll
        for (int t = 0; t < 8; t++) a[t] = buf[jf][P(kk + 64 * jj + 8 * t)];
        __syncthreads();
        {
            float2 w = tw512[8 * jj];
            float2 cw = w;
            a[1] = cmul(a[1], cw);
            #pragma unroll
            for (int t = 2; t < 8; t++) { cw = cmul(cw, w); a[t] = cmul(a[t], cw); }
        }
        bfly8(a, b);
        #pragma unroll
        for (int u = 0; u < 8; u++) buf[jf][P(kk + 8 * jj + 64 * u)] = b[u];
        __syncthreads();

        // ---- stage 2: l=64, twiddles from tw512[lt]; then window in registers ----
        #pragma unroll
        for (int t = 0; t < 8; t++) a[t] = buf[jf][P(8 * lt + t)];
        {
            float2 w = tw512[lt];
            float2 cw = w;
            a[1] = cmul(a[1], cw);
            #pragma unroll
            for (int t = 2; t < 8; t++) { cw = cmul(cw, w); a[t] = cmul(a[t], cw); }
        }
        bfly8(a, b);   // b[u] = z[lt + 64u]; even sample in .x, odd in .y

        // Hann window: h(s) = 0.5 - 0.5 cos(2 pi s/1024); s = 2m (.x), 2m+1 (.y)
        {
            const float R = 0.70710678118654752f;
            float2 e = tw1024[2 * lt];
            float2 o = tw1024[2 * lt + 1];
            #pragma unroll
            for (int u = 0; u < 8; u++) {
                b[u].x *= (0.5f - 0.5f * e.x);
                b[u].y *= (0.5f - 0.5f * o.x);
                float ex = (e.x - e.y) * R, ey = (e.x + e.y) * R; e = make_float2(ex, ey);
                float ox = (o.x - o.y) * R, oy = (o.x + o.y) * R; o = make_float2(ox, oy);
            }
        }

        // ---- OLA: chunk c=3 is first-touched by this frame -> plain store;
        //      then chunks 0,1,2 add. Fixed-c rounds race-free (regions jf+c distinct). ----
        const int offh = ((g << 2) + jf) << 7;   // 128*(4g+jf) in f2 units
        {
            int m6 = lt + (6 << 6), m7 = lt + (7 << 6);
            acc2[offh + m6] = b[6];
            acc2[offh + m7] = b[7];
        }
        __syncthreads();
        #pragma unroll
        for (int c = 0; c < 3; c++) {
            #pragma unroll
            for (int h = 0; h < 2; h++) {
                int u = 2 * c + h;
                int m = lt + (u << 6);
                float2 v = acc2[offh + m];
                v.x += b[u].x; v.y += b[u].y;
                acc2[offh + m] = v;
            }
            __syncthreads();
        }
    }

    // ---- writeout: all plain stores. Head [0,768) -> edge_buf (x>0) or out (x==0,
    //      minus crop). Body+tail [768,4864) -> out (sole owner of those p). ----
    const float* accf = (const float*)acc2;
    float* obase = out + (size_t)bc * OUT_PER_BC;
    const int q0 = tbase << 8;   // 256 * tbase
    if (xb == 0) {
        for (int idx = tid; idx < EDGE_LEN; idx += 256)
            if (idx >= 512) obase[idx - 512] = accf[idx];   // crop y[:, :512]
    } else {
        float* eb = &edge_buf[((size_t)bc * (NBLK - 1) + (xb - 1)) * EDGE_LEN];
        for (int idx = tid; idx < EDGE_LEN; idx += 256) eb[idx] = accf[idx];
    }
    for (int idx2 = tid + EDGE_LEN / 2; idx2 < ACC_F2; idx2 += 256) {
        int p = q0 + 2 * idx2 - 512;
        *(float2*)(obase + p) = acc2[idx2];
    }
}

// out[bc, 4096*x - 512 + i] += edge_buf[bc][x-1][i], x in 1..63
__global__ void edge_add_kernel(float* __restrict__ out) {
    const int bc = blockIdx.y;
    const int x = blockIdx.x + 1;
    const float4* eb = (const float4*)&edge_buf[((size_t)bc * (NBLK - 1) + (x - 1)) * EDGE_LEN];
    float4* op = (float4*)(out + (size_t)bc * OUT_PER_BC + 4096 * x - 512);
    const int i = threadIdx.x;   // 192 threads, 4 floats each = 768
    float4 v = op[i], e = eb[i];
    v.x += e.x; v.y += e.y; v.z += e.z; v.w += e.w;
    op[i] = v;
}

extern "C" void kernel_launch(void* const* d_in, const int* in_sizes, int n_in,
                              void* d_out, int out_size) {
    const float2* in = (const float2*)d_in[0];
    float* out = (float*)d_out;
    dim3 grid(NBLK, 64);   // (t-groups, bc)
    istft_kernel<<<grid, 256>>>(in, out);
    dim3 grid2(NBLK - 1, 64);
    edge_add_kernel<<<grid2, 192>>>(out);
}

// round 10
// speedup vs baseline: 1.4804x; 1.1248x over previous
#include <cuda_runtime.h>
#include <math.h>

// ISTFT: BC=64; F=513; T=1024; n_fft=1024; hop=256.
// R4-proven core: 4 frames in flight, 64-thread team per frame, radix-8
// Stockham x3 in smem, rotation-chain twiddles, smem OLA.
// Edge handling: pre-zeroed overlap strips + atomicAdd head/tail in main
// (no full memset, no dependent edge kernel).

#define FRAMES_PER_CTA 16
#define GROUPS 4
#define ACC_F2  2432          // 4864 floats
#define OUT_PER_BC 262400
#define NBLK 64               // t-group blocks per bc

__device__ __forceinline__ float2 cmul(float2 a, float2 b) {
    return make_float2(a.x * b.x - a.y * b.y, a.x * b.y + a.y * b.x);
}
__device__ __forceinline__ float2 cadd(float2 a, float2 b) { return make_float2(a.x + b.x, a.y + b.y); }
__device__ __forceinline__ float2 csub(float2 a, float2 b) { return make_float2(a.x - b.x, a.y - b.y); }
__device__ __forceinline__ float2 cmuli(float2 a) { return make_float2(-a.y, a.x); }  // * i

__device__ __forceinline__ int P(int i) { return i + (i >> 3); }  // smem pad swizzle

// radix-8 inverse butterfly: b[u] = sum_t a[t] * e^{+2*pi*i*t*u/8}
__device__ __forceinline__ void bfly8(const float2* a, float2* b) {
    const float r = 0.70710678118654752f;
    float2 p0 = cadd(a[0], a[4]), p1 = csub(a[0], a[4]);
    float2 p2 = cadd(a[2], a[6]), p3 = cmuli(csub(a[2], a[6]));
    float2 e0 = cadd(p0, p2), e2 = csub(p0, p2), e1 = cadd(p1, p3), e3 = csub(p1, p3);
    float2 q0 = cadd(a[1], a[5]), q1 = csub(a[1], a[5]);
    float2 q2 = cadd(a[3], a[7]), q3 = cmuli(csub(a[3], a[7]));
    float2 o0 = cadd(q0, q2), o2 = csub(q0, q2), o1 = cadd(q1, q3), o3 = csub(q1, q3);
    b[0] = cadd(e0, o0); b[4] = csub(e0, o0);
    float2 w1 = make_float2(r, r), w3 = make_float2(-r, r);
    float2 t1 = cmul(o1, w1); b[1] = cadd(e1, t1); b[5] = csub(e1, t1);
    float2 t2 = cmuli(o2);    b[2] = cadd(e2, t2); b[6] = csub(e2, t2);
    float2 t3 = cmul(o3, w3); b[3] = cadd(e3, t3); b[7] = csub(e3, t3);
}

// zero the 63 overlap strips per bc: out[bc, 4096x-512 .. 4096x+256), x=1..63
__global__ void zero_strips_kernel(float* __restrict__ out) {
    int e = blockIdx.x * 256 + threadIdx.x;      // float4 index
    if (e >= 64 * 63 * 192) return;
    int i = e % 192;
    int r = e / 192;
    int x = r % 63 + 1;
    int bc = r / 63;
    float4* p = (float4*)(out + (size_t)bc * OUT_PER_BC + 4096 * x - 512);
    p[i] = make_float4(0.f, 0.f, 0.f, 0.f);
}

__global__ void __launch_bounds__(256, 4) istft_kernel(const float2* __restrict__ in,
                                                       float* __restrict__ out) {
    __shared__ float2 buf[4][577];     // per-frame FFT workspace
    __shared__ float2 acc2[ACC_F2];    // overlap-add accumulator
    __shared__ float2 tw512[512];      // e^{+2pi i k/512}
    __shared__ float2 tw1024[513];     // e^{+2pi i k/1024}

    const int tid = threadIdx.x;
    const int bc = blockIdx.y;
    const int xb = blockIdx.x;
    const int tbase = xb * FRAMES_PER_CTA;

    // ---- init tables (fast intrinsics); zero only the add-only head of acc ----
    for (int i = tid; i < 512; i += 256) {
        float s, c;
        __sincosf(6.283185307179586f * (float)i / 512.0f, &s, &c);
        tw512[i] = make_float2(c, s);
    }
    for (int i = tid; i < 513; i += 256) {
        float s, c;
        __sincosf(6.283185307179586f * (float)i / 1024.0f, &s, &c);
        tw1024[i] = make_float2(c, s);
    }
    for (int i = tid; i < 384; i += 256) acc2[i] = make_float2(0.f, 0.f);
    __syncthreads();

    const int jf = tid >> 6;   // frame within group of 4
    const int lt = tid & 63;   // lane within frame's 64-thread FFT team
    const int jj = lt >> 3, kk = lt & 7;
    const float SC = 0.015625f;   // 1/2 pack * 1/512 ifft * sqrt(1024) * 1/2 coeff

    for (int g = 0; g < GROUPS; g++) {
        // ---- load spectra + C2R pack fused; float4 loads (2 frames per load) ----
        {
            const int t0 = tbase + 4 * g;
            const float2* base = in + (size_t)bc * 513 * 1024 + t0;
            for (int idx = tid; idx < 257 * 2; idx += 256) {
                int f = idx >> 1, jp = (idx & 1) << 1;     // jp = 0 or 2 (frame pair)
                float4 X2 = *(const float4*)(base + (size_t)f * 1024 + jp);
                float4 Y2 = *(const float4*)(base + (size_t)(512 - f) * 1024 + jp);
                if (f == 0) { X2.y = 0.f; X2.w = 0.f; Y2.y = 0.f; Y2.w = 0.f; }
                float2 w = tw1024[f];
                #pragma unroll
                for (int s = 0; s < 2; s++) {
                    float2 X = s ? make_float2(X2.z, X2.w) : make_float2(X2.x, X2.y);
                    float2 Y = s ? make_float2(Y2.z, Y2.w) : make_float2(Y2.x, Y2.y);
                    float2 A = make_float2(X.x + Y.x, X.y - Y.y);   // X[f] + conj(X[512-f])
                    float2 D = make_float2(X.x - Y.x, X.y + Y.y);   // X[f] - conj(X[512-f])
                    float2 wD = cmul(w, D);
                    buf[jp + s][P(f)] = make_float2((A.x - wD.y) * SC, (A.y + wD.x) * SC);
                    if (f > 0 && f < 256)   // partner C[512-f] (w' = -conj w)
                        buf[jp + s][P(512 - f)] =
                            make_float2((A.x + wD.y) * SC, (-A.y + wD.x) * SC);
                }
            }
        }
        __syncthreads();

        float2 a[8], b[8];

        // ---- stage 0: l=1, no twiddles. Thread writes exactly its read slots
        //      -> no barrier between read and write. ----
        #pragma unroll
        for (int r_ = 0; r_ < 8; r_++) a[r_] = buf[jf][P(lt + (r_ << 6))];
        bfly8(a, b);
        #pragma unroll
        for (int u = 0; u < 8; u++) buf[jf][P(lt + (u << 6))] = b[u];
        __syncthreads();

        // ---- stage 1: l=8, twiddles by register rotation from tw512[8*jj] ----
        #pragma unroll
        for (int t = 0; t < 8; t++) a[t] = buf[jf][P(kk + 64 * jj + 8 * t)];
        __syncthreads();
        {
            float2 w = tw512[8 * jj];
            float2 cw = w;
            a[1] = cmul(a[1], cw);
            #pragma unroll
            for (int t = 2; t < 8; t++) { cw = cmul(cw, w); a[t] = cmul(a[t], cw); }
        }
        bfly8(a, b);
        #pragma unroll
        for (int u = 0; u < 8; u++) buf[jf][P(kk + 8 * jj + 64 * u)] = b[u];
        __syncthreads();

        // ---- stage 2: l=64, twiddles from tw512[lt]; then window in registers ----
        #pragma unroll
        for (int t = 0; t < 8; t++) a[t] = buf[jf][P(8 * lt + t)];
        {
            float2 w = tw512[lt];
            float2 cw = w;
            a[1] = cmul(a[1], cw);
            #pragma unroll
            for (int t = 2; t < 8; t++) { cw = cmul(cw, w); a[t] = cmul(a[t], cw); }
        }
        bfly8(a, b);   // b[u] = z[lt + 64u]; even sample in .x, odd in .y

        // Hann window: h(s) = 0.5 - 0.5 cos(2 pi s/1024); s = 2m (.x), 2m+1 (.y)
        {
            const float R = 0.70710678118654752f;
            float2 e = tw1024[2 * lt];
            float2 o = tw1024[2 * lt + 1];
            #pragma unroll
            for (int u = 0; u < 8; u++) {
                b[u].x *= (0.5f - 0.5f * e.x);
                b[u].y *= (0.5f - 0.5f * o.x);
                float ex = (e.x - e.y) * R, ey = (e.x + e.y) * R; e = make_float2(ex, ey);
                float ox = (o.x - o.y) * R, oy = (o.x + o.y) * R; o = make_float2(ox, oy);
            }
        }

        // ---- OLA: chunk c=3 first-touched by this frame -> plain store; then
        //      chunks 0,1,2 add. Fixed-c rounds race-free (regions jf+c distinct). ----
        const int offh = ((g << 2) + jf) << 7;   // 128*(4g+jf) in f2 units
        {
            acc2[offh + lt + (6 << 6)] = b[6];
            acc2[offh + lt + (7 << 6)] = b[7];
        }
        __syncthreads();
        #pragma unroll
        for (int c = 0; c < 3; c++) {
            #pragma unroll
            for (int h = 0; h < 2; h++) {
                int u = 2 * c + h;
                int m = lt + (u << 6);
                float2 v = acc2[offh + m];
                v.x += b[u].x; v.y += b[u].y;
                acc2[offh + m] = v;
            }
            __syncthreads();
        }
    }

    // ---- writeout ----
    // head floats [0,768): xb==0 -> sole owner (store, minus crop 512);
    //                      else  -> atomicAdd into pre-zeroed strip xb.
    // body f2 [384,2048): sole owner -> float4 stores.
    // tail f2 [2048,2432): xb==63 -> sole owner (store); else atomicAdd strip xb+1.
    const float* accf = (const float*)acc2;
    float* obase = out + (size_t)bc * OUT_PER_BC;
    const int q0 = tbase << 8;   // 256 * tbase (floats)
    if (xb == 0) {
        for (int idx = tid; idx < 768; idx += 256)
            if (idx >= 512) obase[idx - 512] = accf[idx];
    } else {
        for (int idx = tid; idx < 768; idx += 256)
            atomicAdd(&obase[q0 + idx - 512], accf[idx]);
    }
    for (int k = tid; k < 832; k += 256) {          // body: 1664 f2 as 832 f4
        int idx2 = 384 + 2 * k;
        float4 v = ((const float4*)acc2)[idx2 >> 1];
        *(float4*)(obase + q0 + 2 * idx2 - 512) = v;
    }
    if (xb == NBLK - 1) {
        for (int idx2 = 2048 + tid; idx2 < ACC_F2; idx2 += 256) {
            int p = q0 + 2 * idx2 - 512;
            *(float2*)(obase + p) = acc2[idx2];
        }
    } else {
        for (int idx2 = 2048 + tid; idx2 < ACC_F2; idx2 += 256) {
            int p = q0 + 2 * idx2 - 512;
            float2 v = acc2[idx2];
            atomicAdd(&obase[p], v.x);
            atomicAdd(&obase[p + 1], v.y);
        }
    }
}

extern "C" void kernel_launch(void* const* d_in, const int* in_sizes, int n_in,
                              void* d_out, int out_size) {
    const float2* in = (const float2*)d_in[0];
    float* out = (float*)d_out;
    // 1) zero only the overlap strips (no dependency on main kernel's output)
    int total_f4 = 64 * 63 * 192;
    zero_strips_kernel<<<(total_f4 + 255) / 256, 256>>>(out);
    // 2) main ISTFT
    dim3 grid(NBLK, 64);   // (t-groups, bc)
    istft_kernel<<<grid, 256>>>(in, out);
}

// round 11
// speedup vs baseline: 1.9031x; 1.2855x over previous
#include <cuda_runtime.h>
#include <math.h>

// ISTFT: BC=64; F=513; T=1024; n_fft=1024; hop=256.
// Core: radix-8 Stockham x3; NEW: C2R pack + stage 0 fused in registers via
// conjugate-pair threads over 8 frames (gmem -> registers -> stage-0 output,
// no pack smem round trip). Stages 1-2 + OLA as 2 passes of 4 x 64-thread teams.
// Edges: pre-zeroed overlap strips + atomicAdd (from R10).

#define OUT_PER_BC 262400
#define NBLK 64               // t-group blocks per bc (16 frames each)
#define ACC_F2 2432           // 4864 floats
#define BUFS 578              // buf row stride (f2); mod 16 == 2 -> fused STS conflict-free

// dynamic smem layout (float2 units)
#define OFF_ACC (8 * BUFS)              // 4624
#define OFF_TW  (OFF_ACC + ACC_F2)      // 7056
#define SMEM_F2 (OFF_TW + 513)          // 7569 f2 = 60552 B

__device__ __forceinline__ float2 cmul(float2 a, float2 b) {
    return make_float2(a.x * b.x - a.y * b.y, a.x * b.y + a.y * b.x);
}
__device__ __forceinline__ float2 cadd(float2 a, float2 b) { return make_float2(a.x + b.x, a.y + b.y); }
__device__ __forceinline__ float2 csub(float2 a, float2 b) { return make_float2(a.x - b.x, a.y - b.y); }
__device__ __forceinline__ float2 cmuli(float2 a) { return make_float2(-a.y, a.x); }  // * i

__device__ __forceinline__ int P(int i) { return i + (i >> 3); }  // smem pad swizzle

// radix-8 inverse butterfly: b[u] = sum_t a[t] * e^{+2*pi*i*t*u/8}
__device__ __forceinline__ void bfly8(const float2* a, float2* b) {
    const float r = 0.70710678118654752f;
    float2 p0 = cadd(a[0], a[4]), p1 = csub(a[0], a[4]);
    float2 p2 = cadd(a[2], a[6]), p3 = cmuli(csub(a[2], a[6]));
    float2 e0 = cadd(p0, p2), e2 = csub(p0, p2), e1 = cadd(p1, p3), e3 = csub(p1, p3);
    float2 q0 = cadd(a[1], a[5]), q1 = csub(a[1], a[5]);
    float2 q2 = cadd(a[3], a[7]), q3 = cmuli(csub(a[3], a[7]));
    float2 o0 = cadd(q0, q2), o2 = csub(q0, q2), o1 = cadd(q1, q3), o3 = csub(q1, q3);
    b[0] = cadd(e0, o0); b[4] = csub(e0, o0);
    float2 w1 = make_float2(r, r), w3 = make_float2(-r, r);
    float2 t1 = cmul(o1, w1); b[1] = cadd(e1, t1); b[5] = csub(e1, t1);
    float2 t2 = cmuli(o2);    b[2] = cadd(e2, t2); b[6] = csub(e2, t2);
    float2 t3 = cmul(o3, w3); b[3] = cadd(e3, t3); b[7] = csub(e3, t3);
}

// zero the 63 overlap strips per bc: out[bc, 4096x-512 .. 4096x+256), x=1..63
__global__ void zero_strips_kernel(float* __restrict__ out) {
    int e = blockIdx.x * 256 + threadIdx.x;      // float4 index
    if (e >= 64 * 63 * 192) return;
    int i = e % 192;
    int r = e / 192;
    int x = r % 63 + 1;
    int bc = r / 63;
    float4* p = (float4*)(out + (size_t)bc * OUT_PER_BC + 4096 * x - 512);
    p[i] = make_float4(0.f, 0.f, 0.f, 0.f);
}

__global__ void __launch_bounds__(256, 3) istft_kernel(const float2* __restrict__ in,
                                                       float* __restrict__ out) {
    extern __shared__ float2 sm[];
    float2 (*buf)[BUFS] = (float2(*)[BUFS])sm;   // 8 frame rows
    float2* acc2 = sm + OFF_ACC;                 // overlap-add accumulator
    float2* tw   = sm + OFF_TW;                  // e^{+2pi i k/1024}, k=0..512

    const int tid = threadIdx.x;
    const int bc = blockIdx.y;
    const int xb = blockIdx.x;
    const int tbase = xb * 16;

    // ---- table init; zero only the add-only head of acc (f2 [0,384)) ----
    for (int i = tid; i < 513; i += 256) {
        float s, c;
        __sincosf(6.283185307179586f * (float)i / 1024.0f, &s, &c);
        tw[i] = make_float2(c, s);
    }
    for (int i = tid; i < 384; i += 256) acc2[i] = make_float2(0.f, 0.f);
    __syncthreads();

    const int jf = tid >> 6;        // team id (stages 1-2/OLA)
    const int lt = tid & 63;        // lane within team
    const int jj = lt >> 3, kk = lt & 7;
    const int jp = tid & 7;         // frame within super-group (pack/stage0)
    const int pp = tid >> 3;        // conjugate pair-lane 0..31
    const float SC = 0.015625f;     // 1/2 pack * 1/512 ifft * sqrt(1024) * 1/2 coeff

    for (int sg = 0; sg < 2; sg++) {
        // ==== fused C2R pack + stage 0 (8 frames, registers only) ====
        {
            const float2* base = in + (size_t)bc * 513 * 1024 + tbase + 8 * sg + jp;
            float2 Ca[8], Cb[8], B[8];
            if (pp == 0) {
                // lane 0 set {64u} (+Nyquist) and lane 32 set {32+64u}, both self-conjugate
                float2 Xa[8], Xc[8];
                #pragma unroll
                for (int u = 0; u < 8; u++) Xa[u] = base[(size_t)(64 * u) * 1024];
                #pragma unroll
                for (int u = 0; u < 8; u++) Xc[u] = base[(size_t)(32 + 64 * u) * 1024];
                float2 ny = base[(size_t)512 * 1024];
                Ca[0] = make_float2((Xa[0].x + ny.x) * SC, (Xa[0].x - ny.x) * SC);
                #pragma unroll
                for (int u = 1; u < 8; u++) {
                    float2 X = Xa[u], Y = Xa[8 - u];          // X[512-64u] = Xa[8-u]
                    float2 A = make_float2(X.x + Y.x, X.y - Y.y);
                    float2 D = make_float2(X.x - Y.x, X.y + Y.y);
                    float2 wD = cmul(tw[64 * u], D);
                    Ca[u] = make_float2((A.x - wD.y) * SC, (A.y + wD.x) * SC);
                }
                #pragma unroll
                for (int u = 0; u < 8; u++) {
                    float2 X = Xc[u], Y = Xc[7 - u];          // X[512-32-64u] = Xc[7-u]
                    float2 A = make_float2(X.x + Y.x, X.y - Y.y);
                    float2 D = make_float2(X.x - Y.x, X.y + Y.y);
                    float2 wD = cmul(tw[32 + 64 * u], D);
                    Cb[u] = make_float2((A.x - wD.y) * SC, (A.y + wD.x) * SC);
                }
                bfly8(Ca, B);
                #pragma unroll
                for (int u = 0; u < 8; u++) buf[jp][P(64 * u)] = B[u];
                bfly8(Cb, B);
                #pragma unroll
                for (int u = 0; u < 8; u++) buf[jp][P(32 + 64 * u)] = B[u];
            } else {
                // lanes (pp, 64-pp): bins {pp+64u} and {(64-pp)+64u}, each read once
                float2 Xa[8], Xb[8];
                #pragma unroll
                for (int u = 0; u < 8; u++) Xa[u] = base[(size_t)(pp + 64 * u) * 1024];
                #pragma unroll
                for (int u = 0; u < 8; u++) Xb[u] = base[(size_t)((64 - pp) + 64 * u) * 1024];
                #pragma unroll
                for (int u = 0; u < 8; u++) {
                    float2 X = Xa[u], Y = Xb[7 - u];          // X[512-k] for k = pp+64u
                    float2 A = make_float2(X.x + Y.x, X.y - Y.y);
                    float2 D = make_float2(X.x - Y.x, X.y + Y.y);
                    float2 wD = cmul(tw[pp + 64 * u], D);
                    Ca[u]     = make_float2((A.x - wD.y) * SC, ( A.y + wD.x) * SC);
                    Cb[7 - u] = make_float2((A.x + wD.y) * SC, (-A.y + wD.x) * SC);
                }
                bfly8(Ca, B);
                #pragma unroll
                for (int u = 0; u < 8; u++) buf[jp][P(pp + 64 * u)] = B[u];
                bfly8(Cb, B);
                #pragma unroll
                for (int u = 0; u < 8; u++) buf[jp][P((64 - pp) + 64 * u)] = B[u];
            }
        }
        __syncthreads();

        // ==== stages 1-2 + window + OLA: 2 passes of 4 frames (order-preserving) ====
        for (int pass = 0; pass < 2; pass++) {
            const int fj = 4 * pass + jf;          // buf row (0..7)
            float2 a[8], b[8];

            // ---- stage 1: l=8, twiddles by register rotation from tw[16*jj] ----
            #pragma unroll
            for (int t = 0; t < 8; t++) a[t] = buf[fj][P(kk + 64 * jj + 8 * t)];
            __syncthreads();
            {
                float2 w = tw[16 * jj];
                float2 cw = w;
                a[1] = cmul(a[1], cw);
                #pragma unroll
                for (int t = 2; t < 8; t++) { cw = cmul(cw, w); a[t] = cmul(a[t], cw); }
            }
            bfly8(a, b);
            #pragma unroll
            for (int u = 0; u < 8; u++) buf[fj][P(kk + 8 * jj + 64 * u)] = b[u];
            __syncthreads();

            // ---- stage 2: l=64, twiddles from tw[2*lt]; then window ----
            #pragma unroll
            for (int t = 0; t < 8; t++) a[t] = buf[fj][P(8 * lt + t)];
            {
                float2 w = tw[2 * lt];
                float2 cw = w;
                a[1] = cmul(a[1], cw);
                #pragma unroll
                for (int t = 2; t < 8; t++) { cw = cmul(cw, w); a[t] = cmul(a[t], cw); }
            }
            bfly8(a, b);   // b[u] = z[lt + 64u]; even sample in .x, odd in .y

            // Hann: h(s) = 0.5 - 0.5 cos(2 pi s/1024); rotate by e^{i pi/4} per u
            {
                const float R = 0.70710678118654752f;
                float2 e = tw[2 * lt];
                float2 o = tw[2 * lt + 1];
                #pragma unroll
                for (int u = 0; u < 8; u++) {
                    b[u].x *= (0.5f - 0.5f * e.x);
                    b[u].y *= (0.5f - 0.5f * o.x);
                    float ex = (e.x - e.y) * R, ey = (e.x + e.y) * R; e = make_float2(ex, ey);
                    float ox = (o.x - o.y) * R, oy = (o.x + o.y) * R; o = make_float2(ox, oy);
                }
            }

            // ---- OLA: chunks 6,7 are this frame's first touch -> store; then
            //      chunks 0..5 add in 3 synced rounds (regions distinct per round). ----
            const int offh = ((sg << 3) + (pass << 2) + jf) << 7;   // 128*F in f2 units
            acc2[offh + lt + (6 << 6)] = b[6];
            acc2[offh + lt + (7 << 6)] = b[7];
            __syncthreads();
            #pragma unroll
            for (int c = 0; c < 3; c++) {
                #pragma unroll
                for (int h = 0; h < 2; h++) {
                    int u = 2 * c + h;
                    int m = lt + (u << 6);
                    float2 v = acc2[offh + m];
                    v.x += b[u].x; v.y += b[u].y;
                    acc2[offh + m] = v;
                }
                __syncthreads();
            }
        }
    }

    // ---- writeout (R10-proven) ----
    // head floats [0,768): xb==0 sole owner (store, crop 512); else atomicAdd strip.
    // body f2 [384,2048): sole owner -> float4 stores.
    // tail f2 [2048,2432): xb==63 sole owner (store); else atomicAdd strip xb+1.
    const float* accf = (const float*)acc2;
    float* obase = out + (size_t)bc * OUT_PER_BC;
    const int q0 = tbase << 8;   // 256 * tbase (floats)
    if (xb == 0) {
        for (int idx = tid; idx < 768; idx += 256)
            if (idx >= 512) obase[idx - 512] = accf[idx];
    } else {
        for (int idx = tid; idx < 768; idx += 256)
            atomicAdd(&obase[q0 + idx - 512], accf[idx]);
    }
    for (int k = tid; k < 832; k += 256) {          // body: 1664 f2 as 832 f4
        int idx2 = 384 + 2 * k;
        float4 v = ((const float4*)acc2)[idx2 >> 1];
        *(float4*)(obase + q0 + 2 * idx2 - 512) = v;
    }
    if (xb == NBLK - 1) {
        for (int idx2 = 2048 + tid; idx2 < ACC_F2; idx2 += 256) {
            int p = q0 + 2 * idx2 - 512;
            *(float2*)(obase + p) = acc2[idx2];
        }
    } else {
        for (int idx2 = 2048 + tid; idx2 < ACC_F2; idx2 += 256) {
            int p = q0 + 2 * idx2 - 512;
            float2 v = acc2[idx2];
            atomicAdd(&obase[p], v.x);
            atomicAdd(&obase[p + 1], v.y);
        }
    }
}

extern "C" void kernel_launch(void* const* d_in, const int* in_sizes, int n_in,
                              void* d_out, int out_size) {
    const float2* in = (const float2*)d_in[0];
    float* out = (float*)d_out;
    const int smem_bytes = SMEM_F2 * sizeof(float2);   // 60552
    cudaFuncSetAttribute(istft_kernel, cudaFuncAttributeMaxDynamicSharedMemorySize, smem_bytes);
    // 1) zero only the overlap strips (independent of main kernel)
    int total_f4 = 64 * 63 * 192;
    zero_strips_kernel<<<(total_f4 + 255) / 256, 256>>>(out);
    // 2) main ISTFT
    dim3 grid(NBLK, 64);   // (t-groups, bc)
    istft_kernel<<<grid, 256, smem_bytes>>>(in, out);
}